// round 11
// baseline (speedup 1.0000x reference)
#include <cuda_runtime.h>
#include <cuda_bf16.h>
#include <cstdint>

#define BTOT 256
#define NTOK 196
#define HEADS 16
#define HD 32
#define CDIM 512
#define MROWS (BTOT*NTOK)          // 50176
#define AELEM (MROWS*CDIM)         // 25690112
#define KVWORDS (BTOT*HEADS*NTOK*16)  // 12845056 u32 pair-words

// ---------------- scratch (device globals) ----------------
__device__ __align__(16) uint16_t g_xhi[AELEM];
__device__ __align__(16) uint16_t g_xlo[AELEM];
__device__ __align__(16) uint16_t g_ahi[AELEM];
__device__ __align__(16) uint16_t g_alo[AELEM];
__device__ __align__(16) uint16_t g_wkvh[2*CDIM*CDIM];
__device__ __align__(16) uint16_t g_wkvl[2*CDIM*CDIM];
__device__ __align__(16) uint16_t g_wprh[CDIM*CDIM];
__device__ __align__(16) uint16_t g_wprl[CDIM*CDIM];
// K,V bf16 hi/lo pair-planes: word (n, dpair) = 2 bf16 (d, d+1); layout [b_,h][n][16]
__device__ __align__(16) uint32_t g_kh[KVWORDS];
__device__ __align__(16) uint32_t g_kl[KVWORDS];
__device__ __align__(16) uint32_t g_vh[KVWORDS];
__device__ __align__(16) uint32_t g_vl[KVWORDS];
__device__ float g_bias[HEADS*NTOK*NTOK];

// ---------------- helpers ----------------
__device__ __forceinline__ void bsplit(float x, uint16_t& hi, uint16_t& lo){
    __nv_bfloat16 h = __float2bfloat16(x);
    __nv_bfloat16 l = __float2bfloat16(x - __bfloat162float(h));
    hi = __bfloat16_as_ushort(h);
    lo = __bfloat16_as_ushort(l);
}
__device__ __forceinline__ void bsplit2(float x0, float x1, uint32_t& hi, uint32_t& lo){
    uint16_t h0,l0,h1,l1;
    bsplit(x0,h0,l0); bsplit(x1,h1,l1);
    hi = (uint32_t)h0 | ((uint32_t)h1<<16);
    lo = (uint32_t)l0 | ((uint32_t)l1<<16);
}
__device__ __forceinline__ void mma16(float* c, const uint32_t* a, uint32_t b0, uint32_t b1){
    asm volatile("mma.sync.aligned.m16n8k16.row.col.f32.bf16.bf16.f32 "
        "{%0,%1,%2,%3},{%4,%5,%6,%7},{%8,%9},{%0,%1,%2,%3};"
        : "+f"(c[0]),"+f"(c[1]),"+f"(c[2]),"+f"(c[3])
        : "r"(a[0]),"r"(a[1]),"r"(a[2]),"r"(a[3]),"r"(b0),"r"(b1));
}
__device__ __forceinline__ void cpa16(void* s, const void* g){
    uint32_t a = (uint32_t)__cvta_generic_to_shared(s);
    asm volatile("cp.async.cg.shared.global [%0],[%1],16;"::"r"(a),"l"(g));
}

// ---------------- pre-split x into bf16 hi/lo planes ----------------
__global__ void split_x_kernel(const float* __restrict__ x){
    const int ng = MROWS*64;
    for (int i = blockIdx.x*blockDim.x + threadIdx.x; i < ng; i += gridDim.x*blockDim.x){
        int row = i>>6, k0 = (i&63)*8;
        const float* src = x + (size_t)row*512 + k0;
        uint16_t h[8], l[8];
#pragma unroll
        for (int j = 0; j < 8; j++) bsplit(src[j], h[j], l[j]);
        size_t e = (size_t)row*512 + k0;
        *(uint4*)(g_xhi + e) = *(uint4*)h;
        *(uint4*)(g_xlo + e) = *(uint4*)l;
    }
}

// ---------------- pre-split weights ----------------
__global__ void conv_w_kernel(const float* __restrict__ kvw, const float* __restrict__ prw){
    const int nk = 2*CDIM*64, np = CDIM*64;
    for (int i = blockIdx.x*blockDim.x + threadIdx.x; i < nk+np; i += gridDim.x*blockDim.x){
        const float* W; uint16_t *Ph, *Pl; int gi;
        if (i < nk) { W = kvw; Ph = g_wkvh; Pl = g_wkvl; gi = i; }
        else        { W = prw; Ph = g_wprh; Pl = g_wprl; gi = i-nk; }
        int row = gi>>6, k0 = (gi&63)*8;
        const float* src = W + (size_t)row*512 + k0;
        uint16_t h[8], l[8];
#pragma unroll
        for (int j = 0; j < 8; j++) bsplit(src[j], h[j], l[j]);
        size_t e = (size_t)row*512 + k0;
        *(uint4*)(Ph + e) = *(uint4*)h;
        *(uint4*)(Pl + e) = *(uint4*)l;
    }
}

// ---------------- bias gather ----------------
__global__ void bias_gather_kernel(const float* __restrict__ table){
    for (int i = blockIdx.x*256 + threadIdx.x; i < HEADS*NTOK*NTOK; i += gridDim.x*256) {
        int m = i % NTOK;
        int t = i / NTOK;
        int n = t % NTOK;
        int h = t / NTOK;
        int t1 = n/49, r1 = n%49, h1 = r1/7, w1 = r1%7;
        int t2 = m/49, r2 = m%49, h2 = r2/7, w2 = r2%7;
        int idx = (t1-t2+3)*169 + (h1-h2+6)*13 + (w1-w2+6);
        g_bias[i] = table[idx*HEADS + h];
    }
}

// ---------------- bf16 3-term GEMM: C[M x NT] = A @ W^T + b ----------------
template<int EPI>
__global__ void __launch_bounds__(256,2) gemm_kernel(
    const float* __restrict__ bias, float* __restrict__ out)
{
    extern __shared__ uint32_t smg[];   // 2 stages * 4 planes * 128*20 u32

    const uint16_t* Ahi = (EPI==0) ? g_xhi  : g_ahi;
    const uint16_t* Alo = (EPI==0) ? g_xlo  : g_alo;
    const uint16_t* Bhi = (EPI==0) ? g_wkvh : g_wprh;
    const uint16_t* Blo = (EPI==0) ? g_wkvl : g_wprl;

    int tid = threadIdx.x, lane = tid&31, wid = tid>>5;
    int bn = blockIdx.x*128, bm = blockIdx.y*128;
    int wm = (wid&1)*64, wn = (wid>>1)*32;

    float c[4][4][4] = {};

    int r0i = tid>>2, s0 = tid&3;
    int r1i = (tid+256)>>2, s1 = s0;

    auto fill = [&](int stage, int kb){
        uint32_t* base = smg + stage*10240;
        const uint16_t* srcs[4] = { Ahi, Alo, Bhi, Blo };
        size_t rb[4]  = { (size_t)(bm+r0i), (size_t)(bm+r0i), (size_t)(bn+r0i), (size_t)(bn+r0i) };
        size_t rb2[4] = { (size_t)(bm+r1i), (size_t)(bm+r1i), (size_t)(bn+r1i), (size_t)(bn+r1i) };
#pragma unroll
        for (int p = 0; p < 4; p++) {
            uint32_t* dst = base + p*2560;
            cpa16(dst + r0i*20 + s0*4, srcs[p] + rb[p]*512  + kb + s0*8);
            cpa16(dst + r1i*20 + s1*4, srcs[p] + rb2[p]*512 + kb + s1*8);
        }
        asm volatile("cp.async.commit_group;" ::: "memory");
    };

    fill(0, 0);

    for (int kb = 0; kb < 512; kb += 32) {
        asm volatile("cp.async.wait_group 0;" ::: "memory");
        __syncthreads();
        int s = (kb>>5)&1;
        if (kb + 32 < 512) fill(s^1, kb+32);

        const uint32_t* Ahs = smg + s*10240;
        const uint32_t* Als = Ahs + 2560;
        const uint32_t* Bhs = Ahs + 5120;
        const uint32_t* Bls = Ahs + 7680;

        int c4 = lane&3, rg = lane>>2;
#pragma unroll
        for (int t = 0; t < 2; t++) {
            uint32_t bh[4][2], bl[4][2];
#pragma unroll
            for (int nt = 0; nt < 4; nt++) {
                int baseb = (wn + nt*8 + rg)*20 + t*8;
                bh[nt][0] = Bhs[baseb+c4];  bh[nt][1] = Bhs[baseb+c4+4];
                bl[nt][0] = Bls[baseb+c4];  bl[nt][1] = Bls[baseb+c4+4];
            }
#pragma unroll
            for (int mt = 0; mt < 4; mt++) {
                int basea = (wm + mt*16 + rg)*20 + t*8;
                uint32_t ah[4], al[4];
                ah[0] = Ahs[basea+c4];      ah[1] = Ahs[basea+160+c4];
                ah[2] = Ahs[basea+c4+4];    ah[3] = Ahs[basea+160+c4+4];
                al[0] = Als[basea+c4];      al[1] = Als[basea+160+c4];
                al[2] = Als[basea+c4+4];    al[3] = Als[basea+160+c4+4];
#pragma unroll
                for (int nt = 0; nt < 4; nt++) {
                    mma16(c[mt][nt], ah, bh[nt][0], bh[nt][1]);
                    mma16(c[mt][nt], ah, bl[nt][0], bl[nt][1]);
                    mma16(c[mt][nt], al, bh[nt][0], bh[nt][1]);
                }
            }
        }
    }

    // epilogue
    int c4 = lane&3, rg = lane>>2;
#pragma unroll
    for (int mt = 0; mt < 4; mt++) {
        int rbase = bm + wm + mt*16 + rg;
#pragma unroll
        for (int half = 0; half < 2; half++) {
            int row = rbase + half*8;
            int b_ = row / 196;
            int n  = row % 196;
#pragma unroll
            for (int nt = 0; nt < 4; nt++) {
                int col0 = bn + wn + nt*8 + c4*2;
                float v0 = c[mt][nt][half*2+0] + bias[col0];
                float v1 = c[mt][nt][half*2+1] + bias[col0+1];
                if (EPI == 0) {
                    int kvsel = col0 >> 9;
                    int hh = (col0>>5)&15, dp = (col0&31)>>1;
                    uint32_t hi, lo; bsplit2(v0, v1, hi, lo);
                    uint32_t* dh = kvsel ? g_vh : g_kh;
                    uint32_t* dl = kvsel ? g_vl : g_kl;
                    size_t idx = (((size_t)b_*16+hh)*196+n)*16 + dp;
                    dh[idx] = hi; dl[idx] = lo;
                } else {
                    out[(size_t)row*512 + col0]     = v0;
                    out[(size_t)row*512 + col0 + 1] = v1;
                }
            }
        }
    }
}

// ---------------- fused attention: one block per (b_, h), 13 warps ----------------
// S/P register-resident; bf16 3-term mma16 for QK^T and PV.
// smem: Ksh/Ksl [200][20] u32, Vsh/Vsl [32][108] u32 (transposed V)
__global__ void __launch_bounds__(416,1) attn_kernel(const float* __restrict__ qg){
    extern __shared__ uint32_t smu[];
    uint32_t* Ksh = smu;                 // 4000
    uint32_t* Ksl = smu + 4000;          // 4000
    uint32_t* Vsh = smu + 8000;          // 3456
    uint32_t* Vsl = smu + 11456;         // 3456

    int h = blockIdx.x, b_ = blockIdx.y, b = b_>>6;
    int tid = threadIdx.x, lane = tid&31, wid = tid>>5;
    int c4 = lane&3, rg = lane>>2;

    const uint32_t* kh = g_kh + ((size_t)b_*16+h)*196*16;
    const uint32_t* kl = g_kl + ((size_t)b_*16+h)*196*16;
    const uint32_t* vh = g_vh + ((size_t)b_*16+h)*196*16;
    const uint32_t* vl = g_vl + ((size_t)b_*16+h)*196*16;

    // K into padded smem (rows 196..199 zero)
    for (int i = tid; i < 3200; i += 416) {
        int n = i>>4, p = i&15;
        uint32_t a = 0, bb = 0;
        if (n < 196) { a = kh[n*16+p]; bb = kl[n*16+p]; }
        Ksh[n*20+p] = a;
        Ksl[n*20+p] = bb;
    }
    // zero V smem
    for (int i = tid; i < 3456; i += 416) { Vsh[i]=0; Vsl[i]=0; }
    __syncthreads();
    // transpose V into [d][token-pair] (u16 scatter, one-time)
    {
        uint16_t* Vh16 = (uint16_t*)Vsh;
        uint16_t* Vl16 = (uint16_t*)Vsl;
        for (int i = tid; i < 3136; i += 416) {
            int n = i>>4, p = i&15;
            uint32_t wh = vh[n*16+p], wl = vl[n*16+p];
            int i0 = ((p*2  )*108 + (n>>1))*2 + (n&1);
            int i1 = ((p*2+1)*108 + (n>>1))*2 + (n&1);
            Vh16[i0] = (uint16_t)(wh & 0xffff);
            Vh16[i1] = (uint16_t)(wh >> 16);
            Vl16[i0] = (uint16_t)(wl & 0xffff);
            Vl16[i1] = (uint16_t)(wl >> 16);
        }
    }
    __syncthreads();

    const float* qbase = qg + ((size_t)b*16+h)*196*32;
    const float* bptr  = g_bias + (size_t)h*196*196;
    const float scale = 0.17677669529663687f;

    int r0 = wid*16 + rg, r1 = r0 + 8;
    bool ok0 = r0 < 196, ok1 = r1 < 196;

    // Q fragments (scaled, bf16 hi/lo)
    uint32_t qh[2][4], ql[2][4];
#pragma unroll
    for (int kt = 0; kt < 2; kt++){
        int k0 = kt*16 + c4*2;
        float2 z = make_float2(0.f,0.f);
        float2 q00 = ok0 ? *(const float2*)(qbase + (size_t)r0*32 + k0)     : z;
        float2 q01 = ok0 ? *(const float2*)(qbase + (size_t)r0*32 + k0 + 8) : z;
        float2 q10 = ok1 ? *(const float2*)(qbase + (size_t)r1*32 + k0)     : z;
        float2 q11 = ok1 ? *(const float2*)(qbase + (size_t)r1*32 + k0 + 8) : z;
        bsplit2(q00.x*scale, q00.y*scale, qh[kt][0], ql[kt][0]);
        bsplit2(q10.x*scale, q10.y*scale, qh[kt][1], ql[kt][1]);
        bsplit2(q01.x*scale, q01.y*scale, qh[kt][2], ql[kt][2]);
        bsplit2(q11.x*scale, q11.y*scale, qh[kt][3], ql[kt][3]);
    }

    // S = Q K^T + bias (register resident)
    float v[25][4];
#pragma unroll
    for (int nt = 0; nt < 25; nt++){
        float cfr[4] = {0.f,0.f,0.f,0.f};
#pragma unroll
        for (int kt = 0; kt < 2; kt++){
            int bb = (nt*8+rg)*20 + kt*8;
            uint32_t bh0 = Ksh[bb+c4], bh1 = Ksh[bb+c4+4];
            uint32_t bl0 = Ksl[bb+c4], bl1 = Ksl[bb+c4+4];
            mma16(cfr, qh[kt], bh0, bh1);
            mma16(cfr, qh[kt], bl0, bl1);
            mma16(cfr, ql[kt], bh0, bh1);
        }
        int cc = nt*8 + c4*2;
        bool cok = cc < 196;
        float2 z = make_float2(0.f,0.f);
        float2 bv0 = (cok && ok0) ? *(const float2*)(bptr + (size_t)r0*196 + cc) : z;
        float2 bv1 = (cok && ok1) ? *(const float2*)(bptr + (size_t)r1*196 + cc) : z;
        v[nt][0] = cok ? cfr[0]+bv0.x : -1e30f;
        v[nt][1] = cok ? cfr[1]+bv0.y : -1e30f;
        v[nt][2] = cok ? cfr[2]+bv1.x : -1e30f;
        v[nt][3] = cok ? cfr[3]+bv1.y : -1e30f;
    }

    // softmax in registers (4 lanes per row via shfl)
    float m0 = -1e30f, m1 = -1e30f;
#pragma unroll
    for (int nt = 0; nt < 25; nt++){
        m0 = fmaxf(m0, fmaxf(v[nt][0], v[nt][1]));
        m1 = fmaxf(m1, fmaxf(v[nt][2], v[nt][3]));
    }
    m0 = fmaxf(m0, __shfl_xor_sync(0xffffffffu, m0, 1));
    m0 = fmaxf(m0, __shfl_xor_sync(0xffffffffu, m0, 2));
    m1 = fmaxf(m1, __shfl_xor_sync(0xffffffffu, m1, 1));
    m1 = fmaxf(m1, __shfl_xor_sync(0xffffffffu, m1, 2));
    float s0 = 0.f, s1 = 0.f;
#pragma unroll
    for (int nt = 0; nt < 25; nt++){
        v[nt][0] = __expf(v[nt][0]-m0);
        v[nt][1] = __expf(v[nt][1]-m0);
        v[nt][2] = __expf(v[nt][2]-m1);
        v[nt][3] = __expf(v[nt][3]-m1);
        s0 += v[nt][0] + v[nt][1];
        s1 += v[nt][2] + v[nt][3];
    }
    s0 += __shfl_xor_sync(0xffffffffu, s0, 1);
    s0 += __shfl_xor_sync(0xffffffffu, s0, 2);
    s1 += __shfl_xor_sync(0xffffffffu, s1, 1);
    s1 += __shfl_xor_sync(0xffffffffu, s1, 2);
    float inv0 = 1.f/s0, inv1 = 1.f/s1;

    // O = P V (P frags built from registers)
    float o[4][4] = {};
#pragma unroll
    for (int ch = 0; ch < 13; ch++){
        uint32_t ph[4], pl[4];
        bsplit2(v[2*ch][0], v[2*ch][1], ph[0], pl[0]);
        bsplit2(v[2*ch][2], v[2*ch][3], ph[1], pl[1]);
        if (ch < 12) {
            bsplit2(v[2*ch+1][0], v[2*ch+1][1], ph[2], pl[2]);
            bsplit2(v[2*ch+1][2], v[2*ch+1][3], ph[3], pl[3]);
        } else {
            ph[2]=ph[3]=pl[2]=pl[3]=0u;
        }
#pragma unroll
        for (int dt = 0; dt < 4; dt++){
            int vb = (dt*8+rg)*108 + ch*8;
            uint32_t vh0 = Vsh[vb+c4], vh1 = Vsh[vb+c4+4];
            uint32_t vl0 = Vsl[vb+c4], vl1 = Vsl[vb+c4+4];
            mma16(o[dt], ph, vh0, vh1);
            mma16(o[dt], ph, vl0, vl1);
            mma16(o[dt], pl, vh0, vh1);
        }
    }

    // epilogue: scale by 1/rowsum, bf16-split into planes for gemm<1>
#pragma unroll
    for (int dt = 0; dt < 4; dt++){
        int col = h*32 + dt*8 + c4*2;
        if (ok0){
            uint32_t hi, lo;
            bsplit2(o[dt][0]*inv0, o[dt][1]*inv0, hi, lo);
            size_t e = ((size_t)(b_*196 + r0)*512 + col) >> 1;
            ((uint32_t*)g_ahi)[e] = hi;
            ((uint32_t*)g_alo)[e] = lo;
        }
        if (ok1){
            uint32_t hi, lo;
            bsplit2(o[dt][2]*inv1, o[dt][3]*inv1, hi, lo);
            size_t e = ((size_t)(b_*196 + r1)*512 + col) >> 1;
            ((uint32_t*)g_ahi)[e] = hi;
            ((uint32_t*)g_alo)[e] = lo;
        }
    }
}

extern "C" void kernel_launch(void* const* d_in, const int* in_sizes, int n_in,
                              void* d_out, int out_size) {
    const float* x   = (const float*)d_in[0];
    const float* qg  = (const float*)d_in[1];
    const float* kvw = (const float*)d_in[2];
    const float* kvb = (const float*)d_in[3];
    const float* pw  = (const float*)d_in[4];
    const float* pb  = (const float*)d_in[5];
    const float* bt  = (const float*)d_in[6];
    float* out = (float*)d_out;

    split_x_kernel<<<4096, 256>>>(x);
    conv_w_kernel<<<384, 256>>>(kvw, pw);
    bias_gather_kernel<<<2402, 256>>>(bt);

    const int GSMEM = 81920;
    cudaFuncSetAttribute(gemm_kernel<0>, cudaFuncAttributeMaxDynamicSharedMemorySize, GSMEM);
    cudaFuncSetAttribute(gemm_kernel<1>, cudaFuncAttributeMaxDynamicSharedMemorySize, GSMEM);

    gemm_kernel<0><<<dim3(8,392), 256, GSMEM>>>(kvb, nullptr);

    const int ASMEM = 14912*4;
    cudaFuncSetAttribute(attn_kernel, cudaFuncAttributeMaxDynamicSharedMemorySize, ASMEM);
    attn_kernel<<<dim3(16,256), 416, ASMEM>>>(qg);

    gemm_kernel<1><<<dim3(4,392), 256, GSMEM>>>(pb, out);
}

// round 12
// speedup vs baseline: 1.2478x; 1.2478x over previous
#include <cuda_runtime.h>
#include <cuda_fp16.h>
#include <cstdint>

#define BTOT 256
#define NTOK 196
#define HEADS 16
#define HD 32
#define CDIM 512
#define MROWS (BTOT*NTOK)          // 50176
#define AELEM (MROWS*CDIM)         // 25690112
#define KVWORDS (BTOT*HEADS*NTOK*16)  // u32 fp16-pair words

// ---------------- scratch (device globals) ----------------
__device__ __align__(16) uint16_t g_xhi[AELEM];     // x fp16 hi plane
__device__ __align__(16) uint16_t g_xlo[AELEM];     // x fp16 lo plane
__device__ __align__(16) uint16_t g_ahi[AELEM];     // attn-out fp16 hi
__device__ __align__(16) uint16_t g_alo[AELEM];     // attn-out fp16 lo
__device__ __align__(16) uint16_t g_wkv[2*CDIM*CDIM]; // kv_w fp16 (single plane)
__device__ __align__(16) uint16_t g_wpr[CDIM*CDIM];   // proj_w fp16
// K,V fp16 pair-planes: word (n, dpair) = 2 fp16 (d,d+1); layout [b_,h][n][16]
__device__ __align__(16) uint32_t g_kp[KVWORDS];
__device__ __align__(16) uint32_t g_vp[KVWORDS];
__device__ float g_bias[HEADS*NTOK*NTOK];

// ---------------- helpers ----------------
__device__ __forceinline__ void hsplit(float x, uint16_t& hi, uint16_t& lo){
    __half h = __float2half_rn(x);
    __half l = __float2half_rn(x - __half2float(h));
    hi = __half_as_ushort(h);
    lo = __half_as_ushort(l);
}
__device__ __forceinline__ void hsplit2(float x0, float x1, uint32_t& hi, uint32_t& lo){
    uint16_t h0,l0,h1,l1;
    hsplit(x0,h0,l0); hsplit(x1,h1,l1);
    hi = (uint32_t)h0 | ((uint32_t)h1<<16);
    lo = (uint32_t)l0 | ((uint32_t)l1<<16);
}
__device__ __forceinline__ uint32_t hpack2(float x0, float x1){
    __half2 p = __floats2half2_rn(x0, x1);
    return *(uint32_t*)&p;
}
__device__ __forceinline__ void mma16(float* c, const uint32_t* a, uint32_t b0, uint32_t b1){
    asm volatile("mma.sync.aligned.m16n8k16.row.col.f32.f16.f16.f32 "
        "{%0,%1,%2,%3},{%4,%5,%6,%7},{%8,%9},{%0,%1,%2,%3};"
        : "+f"(c[0]),"+f"(c[1]),"+f"(c[2]),"+f"(c[3])
        : "r"(a[0]),"r"(a[1]),"r"(a[2]),"r"(a[3]),"r"(b0),"r"(b1));
}
__device__ __forceinline__ void cpa16(void* s, const void* g){
    uint32_t a = (uint32_t)__cvta_generic_to_shared(s);
    asm volatile("cp.async.cg.shared.global [%0],[%1],16;"::"r"(a),"l"(g));
}

// ---------------- pre-split x into fp16 hi/lo planes ----------------
__global__ void split_x_kernel(const float* __restrict__ x){
    const int ng = MROWS*64;
    for (int i = blockIdx.x*blockDim.x + threadIdx.x; i < ng; i += gridDim.x*blockDim.x){
        int row = i>>6, k0 = (i&63)*8;
        const float* src = x + (size_t)row*512 + k0;
        uint16_t h[8], l[8];
#pragma unroll
        for (int j = 0; j < 8; j++) hsplit(src[j], h[j], l[j]);
        size_t e = (size_t)row*512 + k0;
        *(uint4*)(g_xhi + e) = *(uint4*)h;
        *(uint4*)(g_xlo + e) = *(uint4*)l;
    }
}

// ---------------- convert weights to single fp16 plane ----------------
__global__ void conv_w_kernel(const float* __restrict__ kvw, const float* __restrict__ prw){
    const int nk = 2*CDIM*64, np = CDIM*64;   // 8-elem granules
    for (int i = blockIdx.x*blockDim.x + threadIdx.x; i < nk+np; i += gridDim.x*blockDim.x){
        const float* W; uint16_t* P; int gi;
        if (i < nk) { W = kvw; P = g_wkv; gi = i; }
        else        { W = prw; P = g_wpr; gi = i-nk; }
        size_t e = (size_t)gi*8;
        const float* src = W + e;
        uint16_t h[8];
#pragma unroll
        for (int j = 0; j < 8; j++) h[j] = __half_as_ushort(__float2half_rn(src[j]));
        *(uint4*)(P + e) = *(uint4*)h;
    }
}

// ---------------- bias gather ----------------
__global__ void bias_gather_kernel(const float* __restrict__ table){
    for (int i = blockIdx.x*256 + threadIdx.x; i < HEADS*NTOK*NTOK; i += gridDim.x*256) {
        int m = i % NTOK;
        int t = i / NTOK;
        int n = t % NTOK;
        int h = t / NTOK;
        int t1 = n/49, r1 = n%49, h1 = r1/7, w1 = r1%7;
        int t2 = m/49, r2 = m%49, h2 = r2/7, w2 = r2%7;
        int idx = (t1-t2+3)*169 + (h1-h2+6)*13 + (w1-w2+6);
        g_bias[i] = table[idx*HEADS + h];
    }
}

// ---------------- fp16 2-term GEMM: C[M x NT] = A @ W^T + b ----------------
// smem per stage (u32, stride 2560/plane): Ah, Al, B.  2 stages.
template<int EPI>
__global__ void __launch_bounds__(256,2) gemm_kernel(
    const float* __restrict__ bias, float* __restrict__ out)
{
    extern __shared__ uint32_t smg[];   // 2 * 3 * 2560 u32 = 61440 B

    const uint16_t* Ahi = (EPI==0) ? g_xhi : g_ahi;
    const uint16_t* Alo = (EPI==0) ? g_xlo : g_alo;
    const uint16_t* Bpl = (EPI==0) ? g_wkv : g_wpr;

    int tid = threadIdx.x, lane = tid&31, wid = tid>>5;
    int bn = blockIdx.x*128, bm = blockIdx.y*128;
    int wm = (wid&1)*64, wn = (wid>>1)*32;

    float c[4][4][4] = {};

    int r0i = tid>>2, s0 = tid&3;
    int r1i = r0i + 64;

    auto fill = [&](int stage, int kb){
        uint32_t* base = smg + stage*7680;
        cpa16(base + r0i*20 + s0*4,        Ahi + (size_t)(bm+r0i)*512 + kb + s0*8);
        cpa16(base + r1i*20 + s0*4,        Ahi + (size_t)(bm+r1i)*512 + kb + s0*8);
        cpa16(base + 2560 + r0i*20 + s0*4, Alo + (size_t)(bm+r0i)*512 + kb + s0*8);
        cpa16(base + 2560 + r1i*20 + s0*4, Alo + (size_t)(bm+r1i)*512 + kb + s0*8);
        cpa16(base + 5120 + r0i*20 + s0*4, Bpl + (size_t)(bn+r0i)*512 + kb + s0*8);
        cpa16(base + 5120 + r1i*20 + s0*4, Bpl + (size_t)(bn+r1i)*512 + kb + s0*8);
        asm volatile("cp.async.commit_group;" ::: "memory");
    };

    fill(0, 0);

    for (int kb = 0; kb < 512; kb += 32) {
        asm volatile("cp.async.wait_group 0;" ::: "memory");
        __syncthreads();
        int s = (kb>>5)&1;
        if (kb + 32 < 512) fill(s^1, kb+32);

        const uint32_t* Ahs = smg + s*7680;
        const uint32_t* Als = Ahs + 2560;
        const uint32_t* Bs  = Ahs + 5120;

        int c4 = lane&3, rg = lane>>2;
#pragma unroll
        for (int t = 0; t < 2; t++) {
            uint32_t bb[4][2];
#pragma unroll
            for (int nt = 0; nt < 4; nt++) {
                int baseb = (wn + nt*8 + rg)*20 + t*8;
                bb[nt][0] = Bs[baseb+c4];  bb[nt][1] = Bs[baseb+c4+4];
            }
#pragma unroll
            for (int mt = 0; mt < 4; mt++) {
                int basea = (wm + mt*16 + rg)*20 + t*8;
                uint32_t ah[4], al[4];
                ah[0] = Ahs[basea+c4];      ah[1] = Ahs[basea+160+c4];
                ah[2] = Ahs[basea+c4+4];    ah[3] = Ahs[basea+160+c4+4];
                al[0] = Als[basea+c4];      al[1] = Als[basea+160+c4];
                al[2] = Als[basea+c4+4];    al[3] = Als[basea+160+c4+4];
#pragma unroll
                for (int nt = 0; nt < 4; nt++) {
                    mma16(c[mt][nt], ah, bb[nt][0], bb[nt][1]);
                    mma16(c[mt][nt], al, bb[nt][0], bb[nt][1]);
                }
            }
        }
    }

    // epilogue
    int c4 = lane&3, rg = lane>>2;
#pragma unroll
    for (int mt = 0; mt < 4; mt++) {
        int rbase = bm + wm + mt*16 + rg;
#pragma unroll
        for (int half = 0; half < 2; half++) {
            int row = rbase + half*8;
            int b_ = row / 196;
            int n  = row % 196;
#pragma unroll
            for (int nt = 0; nt < 4; nt++) {
                int col0 = bn + wn + nt*8 + c4*2;
                float v0 = c[mt][nt][half*2+0] + bias[col0];
                float v1 = c[mt][nt][half*2+1] + bias[col0+1];
                if (EPI == 0) {
                    int kvsel = col0 >> 9;
                    int hh = (col0>>5)&15, dp = (col0&31)>>1;
                    uint32_t* dst = kvsel ? g_vp : g_kp;
                    dst[(((size_t)b_*16+hh)*196+n)*16 + dp] = hpack2(v0, v1);
                } else {
                    out[(size_t)row*512 + col0]     = v0;
                    out[(size_t)row*512 + col0 + 1] = v1;
                }
            }
        }
    }
}

// ---------------- fused attention: one block per (b_, h), 13 warps ----------------
// fp16 2-term; S/P register-resident.
// smem: Ks [200][20] u32, Vs [32][108] u32 (transposed V)
__global__ void __launch_bounds__(416,1) attn_kernel(const float* __restrict__ qg){
    extern __shared__ uint32_t smu[];
    uint32_t* Ks = smu;            // 4000
    uint32_t* Vs = smu + 4000;     // 3456

    int h = blockIdx.x, b_ = blockIdx.y, b = b_>>6;
    int tid = threadIdx.x, lane = tid&31, wid = tid>>5;
    int c4 = lane&3, rg = lane>>2;

    const uint32_t* kp = g_kp + ((size_t)b_*16+h)*196*16;
    const uint32_t* vp = g_vp + ((size_t)b_*16+h)*196*16;

    // K into padded smem (rows 196..199 zero)
    for (int i = tid; i < 3200; i += 416) {
        int n = i>>4, p = i&15;
        uint32_t a = 0;
        if (n < 196) a = kp[n*16+p];
        Ks[n*20+p] = a;
    }
    // zero V smem
    for (int i = tid; i < 3456; i += 416) Vs[i] = 0;
    __syncthreads();
    // transpose V into [d][token-pair]
    {
        uint16_t* V16 = (uint16_t*)Vs;
        for (int i = tid; i < 3136; i += 416) {
            int n = i>>4, p = i&15;
            uint32_t w = vp[n*16+p];
            int i0 = ((p*2  )*108 + (n>>1))*2 + (n&1);
            int i1 = ((p*2+1)*108 + (n>>1))*2 + (n&1);
            V16[i0] = (uint16_t)(w & 0xffff);
            V16[i1] = (uint16_t)(w >> 16);
        }
    }
    __syncthreads();

    const float* qbase = qg + ((size_t)b*16+h)*196*32;
    const float* bptr  = g_bias + (size_t)h*196*196;
    const float scale = 0.17677669529663687f;

    int r0 = wid*16 + rg, r1 = r0 + 8;
    bool ok0 = r0 < 196, ok1 = r1 < 196;

    // Q fragments (scaled, fp16 hi/lo)
    uint32_t qh[2][4], ql[2][4];
#pragma unroll
    for (int kt = 0; kt < 2; kt++){
        int k0 = kt*16 + c4*2;
        float2 z = make_float2(0.f,0.f);
        float2 q00 = ok0 ? *(const float2*)(qbase + (size_t)r0*32 + k0)     : z;
        float2 q01 = ok0 ? *(const float2*)(qbase + (size_t)r0*32 + k0 + 8) : z;
        float2 q10 = ok1 ? *(const float2*)(qbase + (size_t)r1*32 + k0)     : z;
        float2 q11 = ok1 ? *(const float2*)(qbase + (size_t)r1*32 + k0 + 8) : z;
        hsplit2(q00.x*scale, q00.y*scale, qh[kt][0], ql[kt][0]);
        hsplit2(q10.x*scale, q10.y*scale, qh[kt][1], ql[kt][1]);
        hsplit2(q01.x*scale, q01.y*scale, qh[kt][2], ql[kt][2]);
        hsplit2(q11.x*scale, q11.y*scale, qh[kt][3], ql[kt][3]);
    }

    // S = Q K^T + bias (register resident)
    float v[25][4];
#pragma unroll
    for (int nt = 0; nt < 25; nt++){
        float cfr[4] = {0.f,0.f,0.f,0.f};
#pragma unroll
        for (int kt = 0; kt < 2; kt++){
            int bb = (nt*8+rg)*20 + kt*8;
            uint32_t b0 = Ks[bb+c4], b1 = Ks[bb+c4+4];
            mma16(cfr, qh[kt], b0, b1);
            mma16(cfr, ql[kt], b0, b1);
        }
        int cc = nt*8 + c4*2;
        bool cok = cc < 196;
        float2 z = make_float2(0.f,0.f);
        float2 bv0 = (cok && ok0) ? *(const float2*)(bptr + (size_t)r0*196 + cc) : z;
        float2 bv1 = (cok && ok1) ? *(const float2*)(bptr + (size_t)r1*196 + cc) : z;
        v[nt][0] = cok ? cfr[0]+bv0.x : -1e30f;
        v[nt][1] = cok ? cfr[1]+bv0.y : -1e30f;
        v[nt][2] = cok ? cfr[2]+bv1.x : -1e30f;
        v[nt][3] = cok ? cfr[3]+bv1.y : -1e30f;
    }

    // softmax in registers (4 lanes per row via shfl)
    float m0 = -1e30f, m1 = -1e30f;
#pragma unroll
    for (int nt = 0; nt < 25; nt++){
        m0 = fmaxf(m0, fmaxf(v[nt][0], v[nt][1]));
        m1 = fmaxf(m1, fmaxf(v[nt][2], v[nt][3]));
    }
    m0 = fmaxf(m0, __shfl_xor_sync(0xffffffffu, m0, 1));
    m0 = fmaxf(m0, __shfl_xor_sync(0xffffffffu, m0, 2));
    m1 = fmaxf(m1, __shfl_xor_sync(0xffffffffu, m1, 1));
    m1 = fmaxf(m1, __shfl_xor_sync(0xffffffffu, m1, 2));
    float s0 = 0.f, s1 = 0.f;
#pragma unroll
    for (int nt = 0; nt < 25; nt++){
        v[nt][0] = __expf(v[nt][0]-m0);
        v[nt][1] = __expf(v[nt][1]-m0);
        v[nt][2] = __expf(v[nt][2]-m1);
        v[nt][3] = __expf(v[nt][3]-m1);
        s0 += v[nt][0] + v[nt][1];
        s1 += v[nt][2] + v[nt][3];
    }
    s0 += __shfl_xor_sync(0xffffffffu, s0, 1);
    s0 += __shfl_xor_sync(0xffffffffu, s0, 2);
    s1 += __shfl_xor_sync(0xffffffffu, s1, 1);
    s1 += __shfl_xor_sync(0xffffffffu, s1, 2);
    float inv0 = 1.f/s0, inv1 = 1.f/s1;

    // O = P V (P frags built from registers, fp16 hi/lo)
    float o[4][4] = {};
#pragma unroll
    for (int ch = 0; ch < 13; ch++){
        uint32_t ph[4], pl[4];
        hsplit2(v[2*ch][0], v[2*ch][1], ph[0], pl[0]);
        hsplit2(v[2*ch][2], v[2*ch][3], ph[1], pl[1]);
        if (ch < 12) {
            hsplit2(v[2*ch+1][0], v[2*ch+1][1], ph[2], pl[2]);
            hsplit2(v[2*ch+1][2], v[2*ch+1][3], ph[3], pl[3]);
        } else {
            ph[2]=ph[3]=pl[2]=pl[3]=0u;
        }
#pragma unroll
        for (int dt = 0; dt < 4; dt++){
            int vb = (dt*8+rg)*108 + ch*8;
            uint32_t v0 = Vs[vb+c4], v1 = Vs[vb+c4+4];
            mma16(o[dt], ph, v0, v1);
            mma16(o[dt], pl, v0, v1);
        }
    }

    // epilogue: scale by 1/rowsum, fp16-split into planes for gemm<1>
#pragma unroll
    for (int dt = 0; dt < 4; dt++){
        int col = h*32 + dt*8 + c4*2;
        if (ok0){
            uint32_t hi, lo;
            hsplit2(o[dt][0]*inv0, o[dt][1]*inv0, hi, lo);
            size_t e = ((size_t)(b_*196 + r0)*512 + col) >> 1;
            ((uint32_t*)g_ahi)[e] = hi;
            ((uint32_t*)g_alo)[e] = lo;
        }
        if (ok1){
            uint32_t hi, lo;
            hsplit2(o[dt][2]*inv1, o[dt][3]*inv1, hi, lo);
            size_t e = ((size_t)(b_*196 + r1)*512 + col) >> 1;
            ((uint32_t*)g_ahi)[e] = hi;
            ((uint32_t*)g_alo)[e] = lo;
        }
    }
}

extern "C" void kernel_launch(void* const* d_in, const int* in_sizes, int n_in,
                              void* d_out, int out_size) {
    const float* x   = (const float*)d_in[0];
    const float* qg  = (const float*)d_in[1];
    const float* kvw = (const float*)d_in[2];
    const float* kvb = (const float*)d_in[3];
    const float* pw  = (const float*)d_in[4];
    const float* pb  = (const float*)d_in[5];
    const float* bt  = (const float*)d_in[6];
    float* out = (float*)d_out;

    split_x_kernel<<<4096, 256>>>(x);
    conv_w_kernel<<<384, 256>>>(kvw, pw);
    bias_gather_kernel<<<2402, 256>>>(bt);

    const int GSMEM = 61440;
    cudaFuncSetAttribute(gemm_kernel<0>, cudaFuncAttributeMaxDynamicSharedMemorySize, GSMEM);
    cudaFuncSetAttribute(gemm_kernel<1>, cudaFuncAttributeMaxDynamicSharedMemorySize, GSMEM);

    gemm_kernel<0><<<dim3(8,392), 256, GSMEM>>>(kvb, nullptr);

    const int ASMEM = 29824;
    cudaFuncSetAttribute(attn_kernel, cudaFuncAttributeMaxDynamicSharedMemorySize, ASMEM);
    attn_kernel<<<dim3(16,256), 416, ASMEM>>>(qg);

    gemm_kernel<1><<<dim3(4,392), 256, GSMEM>>>(pb, out);
}

// round 13
// speedup vs baseline: 1.3009x; 1.0425x over previous
#include <cuda_runtime.h>
#include <cuda_fp16.h>
#include <cstdint>

#define BTOT 256
#define NTOK 196
#define HEADS 16
#define HD 32
#define CDIM 512
#define MROWS (BTOT*NTOK)          // 50176
#define AELEM (MROWS*CDIM)         // 25690112
#define KVWORDS (BTOT*HEADS*NTOK*16)  // u32 fp16-pair words

// ---------------- scratch (device globals) ----------------
__device__ __align__(16) uint16_t g_xhi[AELEM];     // x fp16 hi plane
__device__ __align__(16) uint16_t g_xlo[AELEM];     // x fp16 lo plane
__device__ __align__(16) uint16_t g_ahi[AELEM];     // attn-out fp16 hi
__device__ __align__(16) uint16_t g_alo[AELEM];     // attn-out fp16 lo
__device__ __align__(16) uint16_t g_wkv[2*CDIM*CDIM]; // kv_w fp16 (single plane)
__device__ __align__(16) uint16_t g_wpr[CDIM*CDIM];   // proj_w fp16
// K,V fp16 pair-planes: word (n, dpair) = 2 fp16 (d,d+1); layout [b_,h][n][16]
__device__ __align__(16) uint32_t g_kp[KVWORDS];
__device__ __align__(16) uint32_t g_vp[KVWORDS];
__device__ float g_bias[HEADS*NTOK*NTOK];

// ---------------- helpers ----------------
__device__ __forceinline__ void hsplit(float x, uint16_t& hi, uint16_t& lo){
    __half h = __float2half_rn(x);
    __half l = __float2half_rn(x - __half2float(h));
    hi = __half_as_ushort(h);
    lo = __half_as_ushort(l);
}
__device__ __forceinline__ void hsplit2(float x0, float x1, uint32_t& hi, uint32_t& lo){
    uint16_t h0,l0,h1,l1;
    hsplit(x0,h0,l0); hsplit(x1,h1,l1);
    hi = (uint32_t)h0 | ((uint32_t)h1<<16);
    lo = (uint32_t)l0 | ((uint32_t)l1<<16);
}
__device__ __forceinline__ uint32_t hpack2(float x0, float x1){
    __half2 p = __floats2half2_rn(x0, x1);
    return *(uint32_t*)&p;
}
__device__ __forceinline__ void mma16(float* c, const uint32_t* a, uint32_t b0, uint32_t b1){
    asm volatile("mma.sync.aligned.m16n8k16.row.col.f32.f16.f16.f32 "
        "{%0,%1,%2,%3},{%4,%5,%6,%7},{%8,%9},{%0,%1,%2,%3};"
        : "+f"(c[0]),"+f"(c[1]),"+f"(c[2]),"+f"(c[3])
        : "r"(a[0]),"r"(a[1]),"r"(a[2]),"r"(a[3]),"r"(b0),"r"(b1));
}
__device__ __forceinline__ void cpa16(void* s, const void* g){
    uint32_t a = (uint32_t)__cvta_generic_to_shared(s);
    asm volatile("cp.async.cg.shared.global [%0],[%1],16;"::"r"(a),"l"(g));
}
__device__ __forceinline__ uint32_t s2u(const void* p){
    return (uint32_t)__cvta_generic_to_shared(p);
}
__device__ __forceinline__ void ldsm4(uint32_t* r, uint32_t a){
    asm volatile("ldmatrix.sync.aligned.m8n8.x4.shared.b16 {%0,%1,%2,%3}, [%4];"
        : "=r"(r[0]),"=r"(r[1]),"=r"(r[2]),"=r"(r[3]) : "r"(a));
}
__device__ __forceinline__ void ldsm2(uint32_t& r0, uint32_t& r1, uint32_t a){
    asm volatile("ldmatrix.sync.aligned.m8n8.x2.shared.b16 {%0,%1}, [%2];"
        : "=r"(r0),"=r"(r1) : "r"(a));
}

// ---------------- pre-split x into fp16 hi/lo planes ----------------
__global__ void split_x_kernel(const float* __restrict__ x){
    const int ng = MROWS*64;
    for (int i = blockIdx.x*blockDim.x + threadIdx.x; i < ng; i += gridDim.x*blockDim.x){
        int row = i>>6, k0 = (i&63)*8;
        const float* src = x + (size_t)row*512 + k0;
        uint16_t h[8], l[8];
#pragma unroll
        for (int j = 0; j < 8; j++) hsplit(src[j], h[j], l[j]);
        size_t e = (size_t)row*512 + k0;
        *(uint4*)(g_xhi + e) = *(uint4*)h;
        *(uint4*)(g_xlo + e) = *(uint4*)l;
    }
}

// ---------------- convert weights to single fp16 plane ----------------
__global__ void conv_w_kernel(const float* __restrict__ kvw, const float* __restrict__ prw){
    const int nk = 2*CDIM*64, np = CDIM*64;   // 8-elem granules
    for (int i = blockIdx.x*blockDim.x + threadIdx.x; i < nk+np; i += gridDim.x*blockDim.x){
        const float* W; uint16_t* P; int gi;
        if (i < nk) { W = kvw; P = g_wkv; gi = i; }
        else        { W = prw; P = g_wpr; gi = i-nk; }
        size_t e = (size_t)gi*8;
        const float* src = W + e;
        uint16_t h[8];
#pragma unroll
        for (int j = 0; j < 8; j++) h[j] = __half_as_ushort(__float2half_rn(src[j]));
        *(uint4*)(P + e) = *(uint4*)h;
    }
}

// ---------------- bias gather ----------------
__global__ void bias_gather_kernel(const float* __restrict__ table){
    for (int i = blockIdx.x*256 + threadIdx.x; i < HEADS*NTOK*NTOK; i += gridDim.x*256) {
        int m = i % NTOK;
        int t = i / NTOK;
        int n = t % NTOK;
        int h = t / NTOK;
        int t1 = n/49, r1 = n%49, h1 = r1/7, w1 = r1%7;
        int t2 = m/49, r2 = m%49, h2 = r2/7, w2 = r2%7;
        int idx = (t1-t2+3)*169 + (h1-h2+6)*13 + (w1-w2+6);
        g_bias[i] = table[idx*HEADS + h];
    }
}

// ---------------- fp16 2-term GEMM: C[M x NT] = A @ W^T + b ----------------
// smem per stage (u32, stride 2560/plane): Ah, Al, B.  2 stages. ldmatrix frag loads.
template<int EPI>
__global__ void __launch_bounds__(256,2) gemm_kernel(
    const float* __restrict__ bias, float* __restrict__ out)
{
    extern __shared__ uint32_t smg[];   // 2 * 3 * 2560 u32 = 61440 B

    const uint16_t* Ahi = (EPI==0) ? g_xhi : g_ahi;
    const uint16_t* Alo = (EPI==0) ? g_xlo : g_alo;
    const uint16_t* Bpl = (EPI==0) ? g_wkv : g_wpr;

    int tid = threadIdx.x, lane = tid&31, wid = tid>>5;
    int bn = blockIdx.x*128, bm = blockIdx.y*128;
    int wm = (wid&1)*64, wn = (wid>>1)*32;

    float c[4][4][4] = {};

    int r0i = tid>>2, s0 = tid&3;
    int r1i = r0i + 64;

    auto fill = [&](int stage, int kb){
        uint32_t* base = smg + stage*7680;
        cpa16(base + r0i*20 + s0*4,        Ahi + (size_t)(bm+r0i)*512 + kb + s0*8);
        cpa16(base + r1i*20 + s0*4,        Ahi + (size_t)(bm+r1i)*512 + kb + s0*8);
        cpa16(base + 2560 + r0i*20 + s0*4, Alo + (size_t)(bm+r0i)*512 + kb + s0*8);
        cpa16(base + 2560 + r1i*20 + s0*4, Alo + (size_t)(bm+r1i)*512 + kb + s0*8);
        cpa16(base + 5120 + r0i*20 + s0*4, Bpl + (size_t)(bn+r0i)*512 + kb + s0*8);
        cpa16(base + 5120 + r1i*20 + s0*4, Bpl + (size_t)(bn+r1i)*512 + kb + s0*8);
        asm volatile("cp.async.commit_group;" ::: "memory");
    };

    fill(0, 0);

    uint32_t smbyte = s2u(smg);
    int lrow = lane&15, lhalf = lane>>4;       // ldmatrix.x4 addressing (A)
    int brow = lane&7,  bhalf = (lane>>3)&1;   // ldmatrix.x2 addressing (B)

    for (int kb = 0; kb < 512; kb += 32) {
        asm volatile("cp.async.wait_group 0;" ::: "memory");
        __syncthreads();
        int s = (kb>>5)&1;
        if (kb + 32 < 512) fill(s^1, kb+32);

        uint32_t bAh = smbyte + s*30720;
        uint32_t bAl = bAh + 10240;
        uint32_t bB  = bAh + 20480;

#pragma unroll
        for (int t = 0; t < 2; t++) {
            uint32_t bb[4][2];
#pragma unroll
            for (int nt = 0; nt < 4; nt++)
                ldsm2(bb[nt][0], bb[nt][1],
                      bB + (wn + nt*8 + brow)*80u + t*32u + bhalf*16u);
#pragma unroll
            for (int mt = 0; mt < 4; mt++) {
                uint32_t abase = (wm + mt*16 + lrow)*80u + t*32u + lhalf*16u;
                uint32_t ah[4], al[4];
                ldsm4(ah, bAh + abase);
                ldsm4(al, bAl + abase);
#pragma unroll
                for (int nt = 0; nt < 4; nt++) {
                    mma16(c[mt][nt], ah, bb[nt][0], bb[nt][1]);
                    mma16(c[mt][nt], al, bb[nt][0], bb[nt][1]);
                }
            }
        }
    }

    // epilogue
    int c4 = lane&3, rg = lane>>2;
#pragma unroll
    for (int mt = 0; mt < 4; mt++) {
        int rbase = bm + wm + mt*16 + rg;
#pragma unroll
        for (int half = 0; half < 2; half++) {
            int row = rbase + half*8;
            int b_ = row / 196;
            int n  = row % 196;
#pragma unroll
            for (int nt = 0; nt < 4; nt++) {
                int col0 = bn + wn + nt*8 + c4*2;
                float v0 = c[mt][nt][half*2+0] + bias[col0];
                float v1 = c[mt][nt][half*2+1] + bias[col0+1];
                if (EPI == 0) {
                    int kvsel = col0 >> 9;
                    int hh = (col0>>5)&15, dp = (col0&31)>>1;
                    uint32_t* dst = kvsel ? g_vp : g_kp;
                    dst[(((size_t)b_*16+hh)*196+n)*16 + dp] = hpack2(v0, v1);
                } else {
                    out[(size_t)row*512 + col0]     = v0;
                    out[(size_t)row*512 + col0 + 1] = v1;
                }
            }
        }
    }
}

// ---------------- fused attention: one block per (b_, h), 13 warps ----------------
// fp16 2-term; S/P register-resident; ldmatrix frag loads.
// smem: Ks [200][20] u32, Vs [32][108] u32 (transposed V)
__global__ void __launch_bounds__(416,1) attn_kernel(const float* __restrict__ qg){
    extern __shared__ uint32_t smu[];
    uint32_t* Ks = smu;            // 4000
    uint32_t* Vs = smu + 4000;     // 3456

    int h = blockIdx.x, b_ = blockIdx.y, b = b_>>6;
    int tid = threadIdx.x, lane = tid&31, wid = tid>>5;
    int c4 = lane&3, rg = lane>>2;

    const uint32_t* kp = g_kp + ((size_t)b_*16+h)*196*16;
    const uint32_t* vp = g_vp + ((size_t)b_*16+h)*196*16;

    // K into padded smem (rows 196..199 zero)
    for (int i = tid; i < 3200; i += 416) {
        int n = i>>4, p = i&15;
        uint32_t a = 0;
        if (n < 196) a = kp[n*16+p];
        Ks[n*20+p] = a;
    }
    // zero V smem
    for (int i = tid; i < 3456; i += 416) Vs[i] = 0;
    __syncthreads();
    // transpose V into [d][token-pair]
    {
        uint16_t* V16 = (uint16_t*)Vs;
        for (int i = tid; i < 3136; i += 416) {
            int n = i>>4, p = i&15;
            uint32_t w = vp[n*16+p];
            int i0 = ((p*2  )*108 + (n>>1))*2 + (n&1);
            int i1 = ((p*2+1)*108 + (n>>1))*2 + (n&1);
            V16[i0] = (uint16_t)(w & 0xffff);
            V16[i1] = (uint16_t)(w >> 16);
        }
    }
    __syncthreads();

    const float* qbase = qg + ((size_t)b*16+h)*196*32;
    const float* bptr  = g_bias + (size_t)h*196*196;
    const float scale = 0.17677669529663687f;

    int r0 = wid*16 + rg, r1 = r0 + 8;
    bool ok0 = r0 < 196, ok1 = r1 < 196;

    uint32_t bK = s2u(Ks), bV = s2u(Vs);
    int brow = lane&7, bhalf = (lane>>3)&1;

    // Q fragments (scaled, fp16 hi/lo)
    uint32_t qh[2][4], ql[2][4];
#pragma unroll
    for (int kt = 0; kt < 2; kt++){
        int k0 = kt*16 + c4*2;
        float2 z = make_float2(0.f,0.f);
        float2 q00 = ok0 ? *(const float2*)(qbase + (size_t)r0*32 + k0)     : z;
        float2 q01 = ok0 ? *(const float2*)(qbase + (size_t)r0*32 + k0 + 8) : z;
        float2 q10 = ok1 ? *(const float2*)(qbase + (size_t)r1*32 + k0)     : z;
        float2 q11 = ok1 ? *(const float2*)(qbase + (size_t)r1*32 + k0 + 8) : z;
        hsplit2(q00.x*scale, q00.y*scale, qh[kt][0], ql[kt][0]);
        hsplit2(q10.x*scale, q10.y*scale, qh[kt][1], ql[kt][1]);
        hsplit2(q01.x*scale, q01.y*scale, qh[kt][2], ql[kt][2]);
        hsplit2(q11.x*scale, q11.y*scale, qh[kt][3], ql[kt][3]);
    }

    // S = Q K^T + bias (register resident)
    float v[25][4];
#pragma unroll
    for (int nt = 0; nt < 25; nt++){
        float cfr[4] = {0.f,0.f,0.f,0.f};
        uint32_t kb0 = bK + (nt*8 + brow)*80u + bhalf*16u;
        uint32_t b0, b1, b2, b3;
        ldsm2(b0, b1, kb0);
        ldsm2(b2, b3, kb0 + 32u);
        mma16(cfr, qh[0], b0, b1);
        mma16(cfr, ql[0], b0, b1);
        mma16(cfr, qh[1], b2, b3);
        mma16(cfr, ql[1], b2, b3);

        int cc = nt*8 + c4*2;
        bool cok = cc < 196;
        float2 z = make_float2(0.f,0.f);
        float2 bv0 = (cok && ok0) ? *(const float2*)(bptr + (size_t)r0*196 + cc) : z;
        float2 bv1 = (cok && ok1) ? *(const float2*)(bptr + (size_t)r1*196 + cc) : z;
        v[nt][0] = cok ? cfr[0]+bv0.x : -1e30f;
        v[nt][1] = cok ? cfr[1]+bv0.y : -1e30f;
        v[nt][2] = cok ? cfr[2]+bv1.x : -1e30f;
        v[nt][3] = cok ? cfr[3]+bv1.y : -1e30f;
    }

    // softmax in registers (4 lanes per row via shfl)
    float m0 = -1e30f, m1 = -1e30f;
#pragma unroll
    for (int nt = 0; nt < 25; nt++){
        m0 = fmaxf(m0, fmaxf(v[nt][0], v[nt][1]));
        m1 = fmaxf(m1, fmaxf(v[nt][2], v[nt][3]));
    }
    m0 = fmaxf(m0, __shfl_xor_sync(0xffffffffu, m0, 1));
    m0 = fmaxf(m0, __shfl_xor_sync(0xffffffffu, m0, 2));
    m1 = fmaxf(m1, __shfl_xor_sync(0xffffffffu, m1, 1));
    m1 = fmaxf(m1, __shfl_xor_sync(0xffffffffu, m1, 2));
    float s0 = 0.f, s1 = 0.f;
#pragma unroll
    for (int nt = 0; nt < 25; nt++){
        v[nt][0] = __expf(v[nt][0]-m0);
        v[nt][1] = __expf(v[nt][1]-m0);
        v[nt][2] = __expf(v[nt][2]-m1);
        v[nt][3] = __expf(v[nt][3]-m1);
        s0 += v[nt][0] + v[nt][1];
        s1 += v[nt][2] + v[nt][3];
    }
    s0 += __shfl_xor_sync(0xffffffffu, s0, 1);
    s0 += __shfl_xor_sync(0xffffffffu, s0, 2);
    s1 += __shfl_xor_sync(0xffffffffu, s1, 1);
    s1 += __shfl_xor_sync(0xffffffffu, s1, 2);
    float inv0 = 1.f/s0, inv1 = 1.f/s1;

    // O = P V (P frags built from registers, fp16 hi/lo)
    float o[4][4] = {};
#pragma unroll
    for (int ch = 0; ch < 13; ch++){
        uint32_t ph[4], pl[4];
        hsplit2(v[2*ch][0], v[2*ch][1], ph[0], pl[0]);
        hsplit2(v[2*ch][2], v[2*ch][3], ph[1], pl[1]);
        if (ch < 12) {
            hsplit2(v[2*ch+1][0], v[2*ch+1][1], ph[2], pl[2]);
            hsplit2(v[2*ch+1][2], v[2*ch+1][3], ph[3], pl[3]);
        } else {
            ph[2]=ph[3]=pl[2]=pl[3]=0u;
        }
#pragma unroll
        for (int dt = 0; dt < 4; dt++){
            uint32_t v0, v1;
            ldsm2(v0, v1, bV + (dt*8 + brow)*432u + ch*32u + bhalf*16u);
            mma16(o[dt], ph, v0, v1);
            mma16(o[dt], pl, v0, v1);
        }
    }

    // epilogue: scale by 1/rowsum, fp16-split into planes for gemm<1>
#pragma unroll
    for (int dt = 0; dt < 4; dt++){
        int col = h*32 + dt*8 + c4*2;
        if (ok0){
            uint32_t hi, lo;
            hsplit2(o[dt][0]*inv0, o[dt][1]*inv0, hi, lo);
            size_t e = ((size_t)(b_*196 + r0)*512 + col) >> 1;
            ((uint32_t*)g_ahi)[e] = hi;
            ((uint32_t*)g_alo)[e] = lo;
        }
        if (ok1){
            uint32_t hi, lo;
            hsplit2(o[dt][2]*inv1, o[dt][3]*inv1, hi, lo);
            size_t e = ((size_t)(b_*196 + r1)*512 + col) >> 1;
            ((uint32_t*)g_ahi)[e] = hi;
            ((uint32_t*)g_alo)[e] = lo;
        }
    }
}

extern "C" void kernel_launch(void* const* d_in, const int* in_sizes, int n_in,
                              void* d_out, int out_size) {
    const float* x   = (const float*)d_in[0];
    const float* qg  = (const float*)d_in[1];
    const float* kvw = (const float*)d_in[2];
    const float* kvb = (const float*)d_in[3];
    const float* pw  = (const float*)d_in[4];
    const float* pb  = (const float*)d_in[5];
    const float* bt  = (const float*)d_in[6];
    float* out = (float*)d_out;

    split_x_kernel<<<4096, 256>>>(x);
    conv_w_kernel<<<384, 256>>>(kvw, pw);
    bias_gather_kernel<<<2402, 256>>>(bt);

    const int GSMEM = 61440;
    cudaFuncSetAttribute(gemm_kernel<0>, cudaFuncAttributeMaxDynamicSharedMemorySize, GSMEM);
    cudaFuncSetAttribute(gemm_kernel<1>, cudaFuncAttributeMaxDynamicSharedMemorySize, GSMEM);

    gemm_kernel<0><<<dim3(8,392), 256, GSMEM>>>(kvb, nullptr);

    const int ASMEM = 29824;
    cudaFuncSetAttribute(attn_kernel, cudaFuncAttributeMaxDynamicSharedMemorySize, ASMEM);
    attn_kernel<<<dim3(16,256), 416, ASMEM>>>(qg);

    gemm_kernel<1><<<dim3(4,392), 256, GSMEM>>>(pb, out);
}